// round 4
// baseline (speedup 1.0000x reference)
#include <cuda_runtime.h>
#include <cstdint>
#include <math.h>

// Problem dims
#define TT 128
#define NN 64
#define DD 512
#define HH 512
#define G3 1536   // 3*H
#define SCAN_CTAS 128

typedef unsigned long long ull;

// ---------------- packed f32x2 helpers ----------------
__device__ __forceinline__ ull fma2(ull a, ull b, ull c) {
    ull d;
    asm("fma.rn.f32x2 %0, %1, %2, %3;" : "=l"(d) : "l"(a), "l"(b), "l"(c));
    return d;
}
__device__ __forceinline__ float lo32(ull v) { return __uint_as_float((unsigned)(v & 0xffffffffu)); }
__device__ __forceinline__ float hi32(ull v) { return __uint_as_float((unsigned)(v >> 32)); }
__device__ __forceinline__ ull pack2(float x, float y) {
    return (((ull)__float_as_uint(y)) << 32) | (ull)__float_as_uint(x);
}

// ---------------- global scratch ----------------
// gi stored [m][g]: g_gi[m * 1536 + g]
__device__ float g_gi[(size_t)TT * NN * G3];

struct __align__(128) PadU { unsigned v; unsigned pad[31]; };
__device__ PadU g_sub[8];    // 2 groups x 4 sub-counters
__device__ PadU g_root[2];   // 2 group roots
__device__ PadU g_epoch[2];  // 2 group epochs

// =====================================================================
// Kernel 1: gi[m, g] = sum_k x[m,k] * w_ih[g,k] + b_ih[g]
// Tiles 64(m) x 64(g), BK=32, 256 threads, 4x4 f2 thread tile.
// =====================================================================
__global__ void __launch_bounds__(256, 2) gemm_gi_kernel(
    const float* __restrict__ x,
    const float* __restrict__ w_ih,
    const float* __restrict__ b_ih)
{
    if (blockIdx.x == 0 && blockIdx.y == 0 && threadIdx.x < 12) {
        if (threadIdx.x < 8) g_sub[threadIdx.x].v = 0;
        else if (threadIdx.x < 10) g_root[threadIdx.x - 8].v = 0;
        else g_epoch[threadIdx.x - 10].v = 0;
    }

    __shared__ ull Gs[64 * 17];
    __shared__ ull Ms[64 * 17];

    const int tid = threadIdx.x;
    const int g0 = blockIdx.x * 64;
    const int m0 = blockIdx.y * 64;
    const int tx = tid & 15;      // -> g group
    const int ty = tid >> 4;      // -> m group

    ull acc[4][4];
#pragma unroll
    for (int i = 0; i < 4; i++)
#pragma unroll
        for (int j = 0; j < 4; j++) acc[i][j] = 0ull;

    for (int k0 = 0; k0 < DD; k0 += 32) {
#pragma unroll
        for (int i = 0; i < 2; i++) {
            int s = tid + i * 256;
            int row = s >> 3, kq = s & 7;
            float4 vg = *reinterpret_cast<const float4*>(&w_ih[(size_t)(g0 + row) * DD + k0 + kq * 4]);
            Gs[row * 17 + kq * 2]     = pack2(vg.x, vg.y);
            Gs[row * 17 + kq * 2 + 1] = pack2(vg.z, vg.w);
            float4 vm = *reinterpret_cast<const float4*>(&x[(size_t)(m0 + row) * DD + k0 + kq * 4]);
            Ms[row * 17 + kq * 2]     = pack2(vm.x, vm.y);
            Ms[row * 17 + kq * 2 + 1] = pack2(vm.z, vm.w);
        }
        __syncthreads();

#pragma unroll
        for (int kk = 0; kk < 16; kk++) {
            ull a[4], b[4];
#pragma unroll
            for (int i = 0; i < 4; i++) a[i] = Ms[(ty + 16 * i) * 17 + kk];
#pragma unroll
            for (int j = 0; j < 4; j++) b[j] = Gs[(tx + 16 * j) * 17 + kk];
#pragma unroll
            for (int i = 0; i < 4; i++)
#pragma unroll
                for (int j = 0; j < 4; j++)
                    acc[i][j] = fma2(a[i], b[j], acc[i][j]);
        }
        __syncthreads();
    }

    float bias[4];
#pragma unroll
    for (int j = 0; j < 4; j++) bias[j] = b_ih[g0 + tx + 16 * j];
#pragma unroll
    for (int i = 0; i < 4; i++) {
        int m = m0 + ty + 16 * i;
#pragma unroll
        for (int j = 0; j < 4; j++) {
            int g = g0 + tx + 16 * j;
            g_gi[(size_t)m * G3 + g] = lo32(acc[i][j]) + hi32(acc[i][j]) + bias[j];
        }
    }
}

// =====================================================================
// Kernel 2: persistent GRU scan, 128 CTAs x 512 threads.
// jb = blockIdx&63 (dims jb*8..+7), rb = blockIdx>>6 (rows rb*32..+31).
// tid = ks*32 + pos: ks = K slice (0..15), pos: rg(0..7) x dg(0..3).
// Thread tile: 4 rows (rg+8i) x 2 dims x 3 gates = 24 f2 acc.
// Two INDEPENDENT barrier groups (rb); tree: 4 subs x 16 CTAs -> root -> epoch.
// =====================================================================
__global__ void __launch_bounds__(512, 1) gru_scan_kernel(
    const float* __restrict__ hxs,
    const float* __restrict__ masks,
    const float* __restrict__ w_hh,
    const float* __restrict__ b_hh,
    float* __restrict__ out)
{
    extern __shared__ float smem[];
    float* hs  = smem;                            // [32][514]
    float* ws  = smem + 32 * 514;                 // [24][516]
    float* red = smem + 32 * 514 + 24 * 516;      // [24][528]

    const int tid = threadIdx.x;
    const int jb = blockIdx.x & 63;
    const int rb = blockIdx.x >> 6;
    const int n0 = rb * 32;
    const int ks = tid >> 5;          // 0..15
    const int pos = tid & 31;
    const int rg = pos >> 2;          // 0..7
    const int dg = pos & 3;           // 0..3
    const int sg = jb & 3;            // sub-counter within group

    // epilogue mapping (threads 0..255): 1 output position each
    const int e_dim  = tid & 7;
    const int e_rloc = tid >> 3;          // valid for tid < 256
    const int e_dimg = jb * 8 + e_dim;
    const int e_i  = (e_rloc >> 3) & 3;
    const int e_rg = e_rloc & 7;
    const int e_dg = e_dim >> 1;
    const int e_dd = e_dim & 1;
    const int e_pcol = e_rg * 4 + e_dg;

    // ---- stage w_hh slice once ----
#pragma unroll
    for (int i = 0; i < 6; i++) {
        int s = tid + i * 512;        // 24 rows x 128 float4
        int lrow = s >> 7;
        int kq = s & 127;
        int g = lrow >> 3;
        int dloc = lrow & 7;
        float4 v = *reinterpret_cast<const float4*>(
            &w_hh[(size_t)(g * HH + jb * 8 + dloc) * HH + kq * 4]);
        *reinterpret_cast<float4*>(&ws[lrow * 516 + kq * 4]) = v;
    }
    const float bh_r = (tid < 256) ? b_hh[e_dimg] : 0.f;
    const float bh_z = (tid < 256) ? b_hh[HH + e_dimg] : 0.f;
    const float bh_n = (tid < 256) ? b_hh[2 * HH + e_dimg] : 0.f;

    const ull* hs_u = reinterpret_cast<const ull*>(hs);
    const ull* ws_u = reinterpret_cast<const ull*>(ws);
    const ull* hp = hs_u + rg * 257 + ks;
    int woff[6];
#pragma unroll
    for (int c = 0; c < 6; c++) {
        int g = c >> 1, dd = c & 1;
        woff[c] = (g * 8 + dg * 2 + dd) * 258 + ks;
    }

    for (int t = 0; t < TT; t++) {
        const float* hprev = (t == 0) ? hxs : (out + (size_t)(t - 1) * NN * HH);

        // ---- prefetch epilogue operands (independent of the dot) ----
        float e_m = 0.f, e_ir = 0.f, e_iz = 0.f, e_inn = 0.f;
        int e_mm = 0, e_n = 0;
        if (tid < 256) {
            e_n = n0 + e_rloc;
            e_mm = t * NN + e_n;
            e_m = __ldg(&masks[e_mm]);
            const float* gi = g_gi + (size_t)e_mm * G3;
            e_ir  = __ldg(&gi[e_dimg]);
            e_iz  = __ldg(&gi[HH + e_dimg]);
            e_inn = __ldg(&gi[2 * HH + e_dimg]);
        }

        // ---- stage h (unmasked): 32 rows x 512 floats ----
#pragma unroll
        for (int i = 0; i < 8; i++) {
            int s = tid + i * 512;
            int row = s >> 7;
            int kq = s & 127;
            float4 v = __ldcg(reinterpret_cast<const float4*>(
                &hprev[(size_t)(n0 + row) * HH + kq * 4]));
            float2* dst = reinterpret_cast<float2*>(&hs[row * 514 + kq * 4]);
            dst[0] = make_float2(v.x, v.y);
            dst[1] = make_float2(v.z, v.w);
        }
        __syncthreads();

        // ---- register-tiled dot: 4 rows x 6 gate-cols, K slice of 16 f2 ----
        ull acc[24];
#pragma unroll
        for (int s = 0; s < 24; s++) acc[s] = 0ull;

#pragma unroll 4
        for (int kk = 0; kk < 16; kk++) {
            const int ko = kk * 16;
            ull a[4];
#pragma unroll
            for (int i = 0; i < 4; i++) a[i] = hp[i * (8 * 257) + ko];
            ull w[6];
#pragma unroll
            for (int c = 0; c < 6; c++) w[c] = ws_u[woff[c] + ko];
#pragma unroll
            for (int i = 0; i < 4; i++)
#pragma unroll
                for (int c = 0; c < 6; c++)
                    acc[i * 6 + c] = fma2(a[i], w[c], acc[i * 6 + c]);
        }

        // ---- write partials (float-collapsed) ----
#pragma unroll
        for (int s = 0; s < 24; s++)
            red[s * 528 + ks * 33 + pos] = lo32(acc[s]) + hi32(acc[s]);
        __syncthreads();

        // ---- epilogue (threads 0..255): reduce 16 slices, gates, store ----
        if (tid < 256) {
            float pr = 0.f, pz = 0.f, pn = 0.f;
            const int sr = (e_i * 6 + 0 + e_dd) * 528 + e_pcol;
            const int sz = (e_i * 6 + 2 + e_dd) * 528 + e_pcol;
            const int sn = (e_i * 6 + 4 + e_dd) * 528 + e_pcol;
#pragma unroll
            for (int k = 0; k < 16; k++) {
                pr += red[sr + k * 33];
                pz += red[sz + k * 33];
                pn += red[sn + k * 33];
            }
            float ghr = pr * e_m + bh_r;
            float ghz = pz * e_m + bh_z;
            float ghn = pn * e_m + bh_n;

            float r = 1.0f / (1.0f + expf(-(e_ir + ghr)));
            float z = 1.0f / (1.0f + expf(-(e_iz + ghz)));
            float nc = tanhf(e_inn + r * ghn);
            float hval = e_m * hs[e_rloc * 514 + e_dimg];
            float hnew = (1.0f - z) * nc + z * hval;

            out[(size_t)e_mm * HH + e_dimg] = hnew;
            if (t == TT - 1)
                out[(size_t)TT * NN * HH + (size_t)e_n * HH + e_dimg] = hnew;
        }

        // ---- tree grid barrier per rb-group (skip after last step) ----
        if (t < TT - 1) {
            __syncthreads();
            if (tid == 0) {
                const unsigned step1 = (unsigned)(t + 1);
                bool wrote = false;
                unsigned old;
                asm volatile("atom.add.acq_rel.gpu.global.u32 %0, [%1], 1;"
                             : "=r"(old) : "l"(&g_sub[rb * 4 + sg].v) : "memory");
                if (old == 16u * step1 - 1u) {
                    unsigned rold;
                    asm volatile("atom.add.acq_rel.gpu.global.u32 %0, [%1], 1;"
                                 : "=r"(rold) : "l"(&g_root[rb].v) : "memory");
                    if (rold == 4u * step1 - 1u) {
                        asm volatile("st.release.gpu.global.u32 [%0], %1;"
                                     :: "l"(&g_epoch[rb].v), "r"(step1) : "memory");
                        wrote = true;
                    }
                }
                if (!wrote) {
                    unsigned e;
                    do {
                        asm volatile("ld.acquire.gpu.global.u32 %0, [%1];"
                                     : "=r"(e) : "l"(&g_epoch[rb].v) : "memory");
                    } while (e < step1);
                }
            }
            __syncthreads();
        }
    }
}

// =====================================================================
extern "C" void kernel_launch(void* const* d_in, const int* in_sizes, int n_in,
                              void* d_out, int out_size)
{
    const float* x      = (const float*)d_in[0];
    const float* hxs    = (const float*)d_in[1];
    const float* hxs_1  = (const float*)d_in[2];
    const float* masks  = (const float*)d_in[3];
    const float* w_ih   = (const float*)d_in[4];
    const float* w_hh   = (const float*)d_in[5];
    const float* b_ih   = (const float*)d_in[6];
    const float* b_hh   = (const float*)d_in[7];
    float* out = (float*)d_out;

    // third output: hxs_1 passthrough
    cudaMemcpyAsync(out + (size_t)(TT * NN + NN) * HH, hxs_1,
                    (size_t)NN * HH * sizeof(float), cudaMemcpyDeviceToDevice);

    // input projections (also resets barrier state)
    dim3 g1(G3 / 64, (TT * NN) / 64);   // (24, 128)
    gemm_gi_kernel<<<g1, 256>>>(x, w_ih, b_ih);

    // persistent scan
    size_t shmem = (size_t)(32 * 514 + 24 * 516 + 24 * 528) * sizeof(float);  // 166,016 B
    cudaFuncSetAttribute(gru_scan_kernel,
                         cudaFuncAttributeMaxDynamicSharedMemorySize, (int)shmem);
    gru_scan_kernel<<<SCAN_CTAS, 512, shmem>>>(hxs, masks, w_hh, b_hh, out);
}

// round 5
// speedup vs baseline: 1.2270x; 1.2270x over previous
#include <cuda_runtime.h>
#include <cstdint>
#include <math.h>

// Problem dims
#define TT 128
#define NN 64
#define DD 512
#define HH 512
#define G3 1536   // 3*H

typedef unsigned long long ull;

// ---------------- packed f32x2 helpers ----------------
__device__ __forceinline__ ull fma2(ull a, ull b, ull c) {
    ull d;
    asm("fma.rn.f32x2 %0, %1, %2, %3;" : "=l"(d) : "l"(a), "l"(b), "l"(c));
    return d;
}
__device__ __forceinline__ float lo32(ull v) { return __uint_as_float((unsigned)(v & 0xffffffffu)); }
__device__ __forceinline__ float hi32(ull v) { return __uint_as_float((unsigned)(v >> 32)); }
__device__ __forceinline__ ull pack2(float x, float y) {
    return (((ull)__float_as_uint(y)) << 32) | (ull)__float_as_uint(x);
}

// ---------------- global scratch ----------------
// gi stored [m][g]: g_gi[m * 1536 + g]
__device__ float g_gi[(size_t)TT * NN * G3];

struct __align__(128) PadU { unsigned v; unsigned pad[31]; };
__device__ PadU g_cnt[4];   // one accumulating counter per row-group

// =====================================================================
// Kernel 1: gi[m, g] = sum_k x[m,k] * w_ih[g,k] + b_ih[g]
// Tiles 64(m) x 64(g), BK=32, 256 threads, 4x4 f2 thread tile.
// =====================================================================
__global__ void __launch_bounds__(256, 2) gemm_gi_kernel(
    const float* __restrict__ x,
    const float* __restrict__ w_ih,
    const float* __restrict__ b_ih)
{
    if (blockIdx.x == 0 && blockIdx.y == 0 && threadIdx.x < 4)
        g_cnt[threadIdx.x].v = 0;

    __shared__ ull Gs[64 * 17];
    __shared__ ull Ms[64 * 17];

    const int tid = threadIdx.x;
    const int g0 = blockIdx.x * 64;
    const int m0 = blockIdx.y * 64;
    const int tx = tid & 15;      // -> g group
    const int ty = tid >> 4;      // -> m group

    ull acc[4][4];
#pragma unroll
    for (int i = 0; i < 4; i++)
#pragma unroll
        for (int j = 0; j < 4; j++) acc[i][j] = 0ull;

    for (int k0 = 0; k0 < DD; k0 += 32) {
#pragma unroll
        for (int i = 0; i < 2; i++) {
            int s = tid + i * 256;
            int row = s >> 3, kq = s & 7;
            float4 vg = *reinterpret_cast<const float4*>(&w_ih[(size_t)(g0 + row) * DD + k0 + kq * 4]);
            Gs[row * 17 + kq * 2]     = pack2(vg.x, vg.y);
            Gs[row * 17 + kq * 2 + 1] = pack2(vg.z, vg.w);
            float4 vm = *reinterpret_cast<const float4*>(&x[(size_t)(m0 + row) * DD + k0 + kq * 4]);
            Ms[row * 17 + kq * 2]     = pack2(vm.x, vm.y);
            Ms[row * 17 + kq * 2 + 1] = pack2(vm.z, vm.w);
        }
        __syncthreads();

#pragma unroll
        for (int kk = 0; kk < 16; kk++) {
            ull a[4], b[4];
#pragma unroll
            for (int i = 0; i < 4; i++) a[i] = Ms[(ty + 16 * i) * 17 + kk];
#pragma unroll
            for (int j = 0; j < 4; j++) b[j] = Gs[(tx + 16 * j) * 17 + kk];
#pragma unroll
            for (int i = 0; i < 4; i++)
#pragma unroll
                for (int j = 0; j < 4; j++)
                    acc[i][j] = fma2(a[i], b[j], acc[i][j]);
        }
        __syncthreads();
    }

    float bias[4];
#pragma unroll
    for (int j = 0; j < 4; j++) bias[j] = b_ih[g0 + tx + 16 * j];
#pragma unroll
    for (int i = 0; i < 4; i++) {
        int m = m0 + ty + 16 * i;
#pragma unroll
        for (int j = 0; j < 4; j++) {
            int g = g0 + tx + 16 * j;
            g_gi[(size_t)m * G3 + g] = lo32(acc[i][j]) + hi32(acc[i][j]) + bias[j];
        }
    }
}

// =====================================================================
// Kernel 2: persistent GRU scan, 128 CTAs x 512 threads.
// 4 row-groups (rb, 16 rows each) x 32 dim-CTAs (jb, 16 dims each).
// tid = ks*32 + pos: ks = K slice (0..15), pos: rg(0..3) + 4*dg(0..7).
// Thread tile: 4 rows (rg+4i) x [2 dims x 3 gates] = 24 f2 acc.
// Barrier per row-group: red.release arrival + ld.acquire counter poll.
// =====================================================================
#define HS_STRIDE 514   // floats (257 ull)
#define WS_STRIDE 514   // floats (257 ull)
#define RS_STRIDE 530   // floats

__global__ void __launch_bounds__(512, 1) gru_scan_kernel(
    const float* __restrict__ hxs,
    const float* __restrict__ masks,
    const float* __restrict__ w_hh,
    const float* __restrict__ b_hh,
    float* __restrict__ out)
{
    extern __shared__ float smem[];
    float* hs  = smem;                                   // [16][514]
    float* ws  = smem + 16 * HS_STRIDE;                  // [48][514]
    float* red = smem + 16 * HS_STRIDE + 48 * WS_STRIDE; // [24][530]

    const int tid = threadIdx.x;
    const int jb = blockIdx.x & 31;       // 16 dims: jb*16 ..
    const int rb = blockIdx.x >> 5;       // 16 rows: rb*16 ..
    const int n0 = rb * 16;
    const int ks = tid >> 5;              // 0..15
    const int pos = tid & 31;
    const int rg = pos & 3;               // row in group of 4
    const int dg = pos >> 2;              // 0..7 dim pair

    // epilogue mapping (threads 0..255): 1 output each (16 rows x 16 dims)
    const int e_dim  = tid & 15;
    const int e_rloc = tid >> 4;              // valid for tid < 256
    const int e_dimg = jb * 16 + e_dim;
    const int e_i  = (e_rloc >> 2) & 3;
    const int e_rg = e_rloc & 3;
    const int e_dg = e_dim >> 1;
    const int e_dd = e_dim & 1;
    const int e_pcol = e_dg * 4 + e_rg;

    // ---- stage w_hh slice once: 48 rows (g*16+dloc) x 512 ----
#pragma unroll
    for (int i = 0; i < 12; i++) {
        int s = tid + i * 512;        // 48 rows x 128 float4
        int lrow = s >> 7;            // 0..47
        int kq = s & 127;
        int g = lrow >> 4;
        int dloc = lrow & 15;
        float4 v = *reinterpret_cast<const float4*>(
            &w_hh[(size_t)(g * HH + jb * 16 + dloc) * HH + kq * 4]);
        float2* dst = reinterpret_cast<float2*>(&ws[lrow * WS_STRIDE + kq * 4]);
        dst[0] = make_float2(v.x, v.y);
        dst[1] = make_float2(v.z, v.w);
    }
    const float bh_r = (tid < 256) ? b_hh[e_dimg] : 0.f;
    const float bh_z = (tid < 256) ? b_hh[HH + e_dimg] : 0.f;
    const float bh_n = (tid < 256) ? b_hh[2 * HH + e_dimg] : 0.f;

    const ull* hs_u = reinterpret_cast<const ull*>(hs);
    const ull* ws_u = reinterpret_cast<const ull*>(ws);
    const ull* hp = hs_u + rg * 257 + ks;
    int woff[6];
#pragma unroll
    for (int c = 0; c < 6; c++) {
        int g = c >> 1, dd = c & 1;
        woff[c] = (g * 16 + dg * 2 + dd) * 257 + ks;
    }

    for (int t = 0; t < TT; t++) {
        const float* hprev = (t == 0) ? hxs : (out + (size_t)(t - 1) * NN * HH);

        // ---- prefetch epilogue operands (independent of the dot) ----
        float e_m = 0.f, e_ir = 0.f, e_iz = 0.f, e_inn = 0.f;
        int e_mm = 0, e_n = 0;
        if (tid < 256) {
            e_n = n0 + e_rloc;
            e_mm = t * NN + e_n;
            e_m = __ldg(&masks[e_mm]);
            const float* gi = g_gi + (size_t)e_mm * G3;
            e_ir  = __ldg(&gi[e_dimg]);
            e_iz  = __ldg(&gi[HH + e_dimg]);
            e_inn = __ldg(&gi[2 * HH + e_dimg]);
        }

        // ---- stage h (unmasked): 16 rows x 512 floats ----
#pragma unroll
        for (int i = 0; i < 4; i++) {
            int s = tid + i * 512;        // 16 rows x 128 float4
            int row = s >> 7;
            int kq = s & 127;
            float4 v = __ldcg(reinterpret_cast<const float4*>(
                &hprev[(size_t)(n0 + row) * HH + kq * 4]));
            float2* dst = reinterpret_cast<float2*>(&hs[row * HS_STRIDE + kq * 4]);
            dst[0] = make_float2(v.x, v.y);
            dst[1] = make_float2(v.z, v.w);
        }
        __syncthreads();

        // ---- register-tiled dot: 4 rows x 6 gate-cols, K slice of 16 f2 ----
        ull acc[24];
#pragma unroll
        for (int s = 0; s < 24; s++) acc[s] = 0ull;

#pragma unroll 4
        for (int kk = 0; kk < 16; kk++) {
            const int ko = kk * 16;
            ull a[4];
#pragma unroll
            for (int i = 0; i < 4; i++) a[i] = hp[i * (4 * 257) + ko];
            ull w[6];
#pragma unroll
            for (int c = 0; c < 6; c++) w[c] = ws_u[woff[c] + ko];
#pragma unroll
            for (int i = 0; i < 4; i++)
#pragma unroll
                for (int c = 0; c < 6; c++)
                    acc[i * 6 + c] = fma2(a[i], w[c], acc[i * 6 + c]);
        }

        // ---- write partials (float-collapsed) ----
#pragma unroll
        for (int s = 0; s < 24; s++)
            red[s * RS_STRIDE + ks * 33 + pos] = lo32(acc[s]) + hi32(acc[s]);
        __syncthreads();

        // ---- epilogue (threads 0..255): reduce 16 slices, gates, store ----
        if (tid < 256) {
            float pr = 0.f, pz = 0.f, pn = 0.f;
            const int sr = (e_i * 6 + 0 + e_dd) * RS_STRIDE + e_pcol;
            const int sz = (e_i * 6 + 2 + e_dd) * RS_STRIDE + e_pcol;
            const int sn = (e_i * 6 + 4 + e_dd) * RS_STRIDE + e_pcol;
#pragma unroll
            for (int k = 0; k < 16; k++) {
                pr += red[sr + k * 33];
                pz += red[sz + k * 33];
                pn += red[sn + k * 33];
            }
            float ghr = pr * e_m + bh_r;
            float ghz = pz * e_m + bh_z;
            float ghn = pn * e_m + bh_n;

            float r = 1.0f / (1.0f + expf(-(e_ir + ghr)));
            float z = 1.0f / (1.0f + expf(-(e_iz + ghz)));
            float nc = tanhf(e_inn + r * ghn);
            float hval = e_m * hs[e_rloc * HS_STRIDE + e_dimg];
            float hnew = (1.0f - z) * nc + z * hval;

            out[(size_t)e_mm * HH + e_dimg] = hnew;
            if (t == TT - 1)
                out[(size_t)TT * NN * HH + (size_t)e_n * HH + e_dimg] = hnew;
        }

        // ---- group barrier: red.release arrival + acquire poll ----
        if (t < TT - 1) {
            __syncthreads();
            if (tid == 0) {
                unsigned one = 1u;
                asm volatile("red.release.gpu.global.add.u32 [%0], %1;"
                             :: "l"(&g_cnt[rb].v), "r"(one) : "memory");
                const unsigned tgt = 32u * (unsigned)(t + 1);
                unsigned e;
                do {
                    asm volatile("ld.acquire.gpu.global.u32 %0, [%1];"
                                 : "=r"(e) : "l"(&g_cnt[rb].v) : "memory");
                } while (e < tgt);
            }
            __syncthreads();
        }
    }
}

// =====================================================================
extern "C" void kernel_launch(void* const* d_in, const int* in_sizes, int n_in,
                              void* d_out, int out_size)
{
    const float* x      = (const float*)d_in[0];
    const float* hxs    = (const float*)d_in[1];
    const float* hxs_1  = (const float*)d_in[2];
    const float* masks  = (const float*)d_in[3];
    const float* w_ih   = (const float*)d_in[4];
    const float* w_hh   = (const float*)d_in[5];
    const float* b_ih   = (const float*)d_in[6];
    const float* b_hh   = (const float*)d_in[7];
    float* out = (float*)d_out;

    // third output: hxs_1 passthrough
    cudaMemcpyAsync(out + (size_t)(TT * NN + NN) * HH, hxs_1,
                    (size_t)NN * HH * sizeof(float), cudaMemcpyDeviceToDevice);

    // input projections (also resets barrier counters)
    dim3 g1(G3 / 64, (TT * NN) / 64);   // (24, 128)
    gemm_gi_kernel<<<g1, 256>>>(x, w_ih, b_ih);

    // persistent scan
    size_t shmem = (size_t)(16 * HS_STRIDE + 48 * WS_STRIDE + 24 * RS_STRIDE)
                   * sizeof(float);   // 182,464 B
    cudaFuncSetAttribute(gru_scan_kernel,
                         cudaFuncAttributeMaxDynamicSharedMemorySize, (int)shmem);
    gru_scan_kernel<<<128, 512, shmem>>>(hxs, masks, w_hh, b_hh, out);
}

// round 6
// speedup vs baseline: 1.3176x; 1.0738x over previous
#include <cuda_runtime.h>
#include <cstdint>
#include <math.h>

// Problem dims
#define TT 128
#define NN 64
#define DD 512
#define HH 512
#define G3 1536   // 3*H

typedef unsigned long long ull;

// ---------------- packed f32x2 helpers ----------------
__device__ __forceinline__ ull fma2(ull a, ull b, ull c) {
    ull d;
    asm("fma.rn.f32x2 %0, %1, %2, %3;" : "=l"(d) : "l"(a), "l"(b), "l"(c));
    return d;
}
__device__ __forceinline__ float lo32(ull v) { return __uint_as_float((unsigned)(v & 0xffffffffu)); }
__device__ __forceinline__ float hi32(ull v) { return __uint_as_float((unsigned)(v >> 32)); }
__device__ __forceinline__ ull pack2(float x, float y) {
    return (((ull)__float_as_uint(y)) << 32) | (ull)__float_as_uint(x);
}

// ---------------- global scratch ----------------
// gi stored [m][g]: g_gi[m * 1536 + g]
__device__ float g_gi[(size_t)TT * NN * G3];

struct __align__(128) PadU { unsigned v; unsigned pad[31]; };
__device__ PadU g_cnt[4];   // one accumulating counter per row-group

// =====================================================================
// Kernel 1: gi[m, g] = sum_k x[m,k] * w_ih[g,k] + b_ih[g]
// Tiles 128(m) x 64(g), BK=32, 256 threads, 8x4 f2 thread tile, occ 2.
// =====================================================================
__global__ void __launch_bounds__(256, 2) gemm_gi_kernel(
    const float* __restrict__ x,
    const float* __restrict__ w_ih,
    const float* __restrict__ b_ih)
{
    if (blockIdx.x == 0 && blockIdx.y == 0 && threadIdx.x < 4)
        g_cnt[threadIdx.x].v = 0;

    __shared__ ull Ms[128 * 17];   // x rows (m)
    __shared__ ull Gs[64 * 17];    // w_ih rows (g)

    const int tid = threadIdx.x;
    const int g0 = blockIdx.x * 64;
    const int m0 = blockIdx.y * 128;
    const int tx = tid & 15;      // -> g group
    const int ty = tid >> 4;      // -> m group

    ull acc[8][4];
#pragma unroll
    for (int i = 0; i < 8; i++)
#pragma unroll
        for (int j = 0; j < 4; j++) acc[i][j] = 0ull;

    for (int k0 = 0; k0 < DD; k0 += 32) {
#pragma unroll
        for (int i = 0; i < 4; i++) {
            int s = tid + i * 256;
            int row = s >> 3, kq = s & 7;
            float4 vm = *reinterpret_cast<const float4*>(&x[(size_t)(m0 + row) * DD + k0 + kq * 4]);
            Ms[row * 17 + kq * 2]     = pack2(vm.x, vm.y);
            Ms[row * 17 + kq * 2 + 1] = pack2(vm.z, vm.w);
        }
#pragma unroll
        for (int i = 0; i < 2; i++) {
            int s = tid + i * 256;
            int row = s >> 3, kq = s & 7;
            float4 vg = *reinterpret_cast<const float4*>(&w_ih[(size_t)(g0 + row) * DD + k0 + kq * 4]);
            Gs[row * 17 + kq * 2]     = pack2(vg.x, vg.y);
            Gs[row * 17 + kq * 2 + 1] = pack2(vg.z, vg.w);
        }
        __syncthreads();

#pragma unroll
        for (int kk = 0; kk < 16; kk++) {
            ull a[8], b[4];
#pragma unroll
            for (int i = 0; i < 8; i++) a[i] = Ms[(ty + 16 * i) * 17 + kk];
#pragma unroll
            for (int j = 0; j < 4; j++) b[j] = Gs[(tx + 16 * j) * 17 + kk];
#pragma unroll
            for (int i = 0; i < 8; i++)
#pragma unroll
                for (int j = 0; j < 4; j++)
                    acc[i][j] = fma2(a[i], b[j], acc[i][j]);
        }
        __syncthreads();
    }

    float bias[4];
#pragma unroll
    for (int j = 0; j < 4; j++) bias[j] = b_ih[g0 + tx + 16 * j];
#pragma unroll
    for (int i = 0; i < 8; i++) {
        int m = m0 + ty + 16 * i;
#pragma unroll
        for (int j = 0; j < 4; j++) {
            int g = g0 + tx + 16 * j;
            g_gi[(size_t)m * G3 + g] = lo32(acc[i][j]) + hi32(acc[i][j]) + bias[j];
        }
    }
}

// =====================================================================
// Kernel 2: persistent GRU scan, 128 CTAs x 512 threads.
// 4 row-groups (rb, 16 rows each) x 32 dim-CTAs (jb, 16 dims each).
// tid = ks*32 + pos: ks = K slice (0..15), pos: rg(0..3) + 4*dg(0..7).
// Thread k-map: f2 slots {2ks, 2ks+1} + 32*kk (kk 0..7) -> LDS.128 loads.
// Thread tile: 4 rows x [2 dims x 3 gates] = 24 f2 acc.
// Barrier per row-group: red.release arrival + ld.acquire counter poll.
// =====================================================================
#define HS_STRIDE 516   // floats (129 ulonglong2)
#define WS_STRIDE 516
#define RS_STRIDE 530

__global__ void __launch_bounds__(512, 1) gru_scan_kernel(
    const float* __restrict__ hxs,
    const float* __restrict__ masks,
    const float* __restrict__ w_hh,
    const float* __restrict__ b_hh,
    float* __restrict__ out)
{
    extern __shared__ float smem[];
    float* hs  = smem;                                   // [16][516]
    float* ws  = smem + 16 * HS_STRIDE;                  // [48][516]
    float* red = smem + 16 * HS_STRIDE + 48 * WS_STRIDE; // [24][530]

    const int tid = threadIdx.x;
    const int jb = blockIdx.x & 31;       // 16 dims: jb*16 ..
    const int rb = blockIdx.x >> 5;       // 16 rows: rb*16 ..
    const int n0 = rb * 16;
    const int ks = tid >> 5;              // 0..15
    const int pos = tid & 31;
    const int rg = pos & 3;               // row in group of 4
    const int dg = pos >> 2;              // 0..7 dim pair

    // epilogue mapping (threads 0..255): 1 output each (16 rows x 16 dims)
    const int e_dim  = tid & 15;
    const int e_rloc = tid >> 4;              // valid for tid < 256
    const int e_dimg = jb * 16 + e_dim;
    const int e_i  = (e_rloc >> 2) & 3;
    const int e_rg = e_rloc & 3;
    const int e_dg = e_dim >> 1;
    const int e_dd = e_dim & 1;
    const int e_pcol = e_dg * 4 + e_rg;

    // ---- stage w_hh slice once: 48 rows (g*16+dloc) x 512 ----
#pragma unroll
    for (int i = 0; i < 12; i++) {
        int s = tid + i * 512;        // 48 rows x 128 float4
        int lrow = s >> 7;            // 0..47
        int kq = s & 127;
        int g = lrow >> 4;
        int dloc = lrow & 15;
        float4 v = *reinterpret_cast<const float4*>(
            &w_hh[(size_t)(g * HH + jb * 16 + dloc) * HH + kq * 4]);
        *reinterpret_cast<float4*>(&ws[lrow * WS_STRIDE + kq * 4]) = v;
    }
    const float bh_r = (tid < 256) ? b_hh[e_dimg] : 0.f;
    const float bh_z = (tid < 256) ? b_hh[HH + e_dimg] : 0.f;
    const float bh_n = (tid < 256) ? b_hh[2 * HH + e_dimg] : 0.f;

    const ulonglong2* hs_v = reinterpret_cast<const ulonglong2*>(hs);
    const ulonglong2* ws_v = reinterpret_cast<const ulonglong2*>(ws);
    const ulonglong2* hp = hs_v + rg * 129 + ks;   // row stride 4*129 per i
    int woff[6];
#pragma unroll
    for (int c = 0; c < 6; c++) {
        int g = c >> 1, dd = c & 1;
        woff[c] = (g * 16 + dg * 2 + dd) * 129 + ks;
    }

    for (int t = 0; t < TT; t++) {
        const float* hprev = (t == 0) ? hxs : (out + (size_t)(t - 1) * NN * HH);

        // ---- prefetch epilogue operands (independent of the dot) ----
        float e_m = 0.f, e_ir = 0.f, e_iz = 0.f, e_inn = 0.f;
        int e_mm = 0, e_n = 0;
        if (tid < 256) {
            e_n = n0 + e_rloc;
            e_mm = t * NN + e_n;
            e_m = __ldg(&masks[e_mm]);
            const float* gi = g_gi + (size_t)e_mm * G3;
            e_ir  = __ldg(&gi[e_dimg]);
            e_iz  = __ldg(&gi[HH + e_dimg]);
            e_inn = __ldg(&gi[2 * HH + e_dimg]);
        }

        // ---- stage h (unmasked): 16 rows x 512 floats ----
#pragma unroll
        for (int i = 0; i < 4; i++) {
            int s = tid + i * 512;        // 16 rows x 128 float4
            int row = s >> 7;
            int kq = s & 127;
            float4 v = __ldcg(reinterpret_cast<const float4*>(
                &hprev[(size_t)(n0 + row) * HH + kq * 4]));
            *reinterpret_cast<float4*>(&hs[row * HS_STRIDE + kq * 4]) = v;
        }
        __syncthreads();

        // ---- register-tiled dot: 4 rows x 6 gate-cols, LDS.128 k pairs ----
        ull acc[24];
#pragma unroll
        for (int s = 0; s < 24; s++) acc[s] = 0ull;

#pragma unroll 2
        for (int kk = 0; kk < 8; kk++) {
            const int ko = kk * 16;
            ulonglong2 a2[4];
#pragma unroll
            for (int i = 0; i < 4; i++) a2[i] = hp[i * (4 * 129) + ko];
            ulonglong2 w2[6];
#pragma unroll
            for (int c = 0; c < 6; c++) w2[c] = ws_v[woff[c] + ko];
#pragma unroll
            for (int i = 0; i < 4; i++)
#pragma unroll
                for (int c = 0; c < 6; c++) {
                    acc[i * 6 + c] = fma2(a2[i].x, w2[c].x, acc[i * 6 + c]);
                    acc[i * 6 + c] = fma2(a2[i].y, w2[c].y, acc[i * 6 + c]);
                }
        }

        // ---- write partials (float-collapsed) ----
#pragma unroll
        for (int s = 0; s < 24; s++)
            red[s * RS_STRIDE + ks * 33 + pos] = lo32(acc[s]) + hi32(acc[s]);
        __syncthreads();

        // ---- epilogue (threads 0..255): reduce 16 slices, gates, store ----
        if (tid < 256) {
            float pr = 0.f, pz = 0.f, pn = 0.f;
            const int sr = (e_i * 6 + 0 + e_dd) * RS_STRIDE + e_pcol;
            const int sz = (e_i * 6 + 2 + e_dd) * RS_STRIDE + e_pcol;
            const int sn = (e_i * 6 + 4 + e_dd) * RS_STRIDE + e_pcol;
#pragma unroll
            for (int k = 0; k < 16; k++) {
                pr += red[sr + k * 33];
                pz += red[sz + k * 33];
                pn += red[sn + k * 33];
            }
            float ghr = pr * e_m + bh_r;
            float ghz = pz * e_m + bh_z;
            float ghn = pn * e_m + bh_n;

            float r = 1.0f / (1.0f + expf(-(e_ir + ghr)));
            float z = 1.0f / (1.0f + expf(-(e_iz + ghz)));
            float nc = tanhf(e_inn + r * ghn);
            float hval = e_m * hs[e_rloc * HS_STRIDE + e_dimg];
            float hnew = (1.0f - z) * nc + z * hval;

            out[(size_t)e_mm * HH + e_dimg] = hnew;
            if (t == TT - 1)
                out[(size_t)TT * NN * HH + (size_t)e_n * HH + e_dimg] = hnew;
        }

        // ---- group barrier: red.release arrival + acquire poll ----
        if (t < TT - 1) {
            __syncthreads();
            if (tid == 0) {
                unsigned one = 1u;
                asm volatile("red.release.gpu.global.add.u32 [%0], %1;"
                             :: "l"(&g_cnt[rb].v), "r"(one) : "memory");
                const unsigned tgt = 32u * (unsigned)(t + 1);
                unsigned e;
                do {
                    asm volatile("ld.acquire.gpu.global.u32 %0, [%1];"
                                 : "=r"(e) : "l"(&g_cnt[rb].v) : "memory");
                } while (e < tgt);
            }
            __syncthreads();
        }
    }
}

// =====================================================================
extern "C" void kernel_launch(void* const* d_in, const int* in_sizes, int n_in,
                              void* d_out, int out_size)
{
    const float* x      = (const float*)d_in[0];
    const float* hxs    = (const float*)d_in[1];
    const float* hxs_1  = (const float*)d_in[2];
    const float* masks  = (const float*)d_in[3];
    const float* w_ih   = (const float*)d_in[4];
    const float* w_hh   = (const float*)d_in[5];
    const float* b_ih   = (const float*)d_in[6];
    const float* b_hh   = (const float*)d_in[7];
    float* out = (float*)d_out;

    // third output: hxs_1 passthrough
    cudaMemcpyAsync(out + (size_t)(TT * NN + NN) * HH, hxs_1,
                    (size_t)NN * HH * sizeof(float), cudaMemcpyDeviceToDevice);

    // input projections (also resets barrier counters)
    dim3 g1(G3 / 64, (TT * NN) / 128);   // (24, 64)
    gemm_gi_kernel<<<g1, 256>>>(x, w_ih, b_ih);

    // persistent scan
    size_t shmem = (size_t)(16 * HS_STRIDE + 48 * WS_STRIDE + 24 * RS_STRIDE)
                   * sizeof(float);   // 182,976 B
    cudaFuncSetAttribute(gru_scan_kernel,
                         cudaFuncAttributeMaxDynamicSharedMemorySize, (int)shmem);
    gru_scan_kernel<<<128, 512, shmem>>>(hxs, masks, w_hh, b_hh, out);
}